// round 2
// baseline (speedup 1.0000x reference)
#include <cuda_runtime.h>
#include <math.h>

#define H    1024
#define NH   16
#define NKV  8
#define HD   128
#define II   3072
#define MAXS 16
#define LL   5
#define EPS  1e-6f

// Residual / activation scratch (allocation-free: __device__ globals)
__device__ float g_x[H];
__device__ float g_h[H];          // normalized hidden (rms(x, w) for current use)
__device__ float g_qraw[NH * HD];
__device__ float g_kraw[NKV * HD];
__device__ float g_vraw[NKV * HD];
__device__ float g_attn[NH * HD];
__device__ float g_t[II];

__device__ __forceinline__ float warp_sum(float v) {
#pragma unroll
    for (int o = 16; o; o >>= 1) v += __shfl_xor_sync(0xffffffffu, v, o);
    return v;
}

__global__ void init_x(const float* __restrict__ hs) {
    g_x[threadIdx.x] = hs[threadIdx.x];
}

// ---------------------------------------------------------------------------
// norm: g_h = rms(g_x, w).  1 block x 1024.
// ---------------------------------------------------------------------------
__global__ void norm_kernel(const float* __restrict__ w) {
    __shared__ float red[32];
    int tid = threadIdx.x;
    float xv = g_x[tid];
    float ssq = warp_sum(xv * xv);
    int lane = tid & 31, wp = tid >> 5;
    if (lane == 0) red[wp] = ssq;
    __syncthreads();
    if (wp == 0) {
        float t = red[lane];
        t = warp_sum(t);
        if (lane == 0) red[0] = rsqrtf(t * (1.f / H) + EPS);
    }
    __syncthreads();
    g_h[tid] = xv * red[0] * w[tid];
}

// ---------------------------------------------------------------------------
// QKV GEMV: block-per-row.  grid 4096 x 256; each thread one float4 of W and h.
// rows: [0,2048) -> q, [2048,3072) -> k, [3072,4096) -> v
// ---------------------------------------------------------------------------
__global__ void __launch_bounds__(256) qkv_kernel(const float* __restrict__ wq,
                                                  const float* __restrict__ wk,
                                                  const float* __restrict__ wv) {
    __shared__ float red[8];
    int row = blockIdx.x;
    int tid = threadIdx.x, lane = tid & 31, wp = tid >> 5;

    const float* wrow;
    float* outp;
    if (row < NH * HD)                 { wrow = wq + (size_t)row * H; outp = g_qraw + row; }
    else if (row < NH * HD + NKV * HD) { int r = row - NH * HD; wrow = wk + (size_t)r * H; outp = g_kraw + r; }
    else                               { int r = row - NH * HD - NKV * HD; wrow = wv + (size_t)r * H; outp = g_vraw + r; }

    float4 a = ((const float4*)wrow)[tid];
    float4 b = ((const float4*)g_h)[tid];
    float acc = a.x * b.x + a.y * b.y + a.z * b.z + a.w * b.w;
    acc = warp_sum(acc);
    if (lane == 0) red[wp] = acc;
    __syncthreads();
    if (tid == 0) {
        float tot = 0.f;
#pragma unroll
        for (int i = 0; i < 8; i++) tot += red[i];
        *outp = tot;
    }
}

// ---------------------------------------------------------------------------
// Attention: q/k norm + RoPE + cache write + softmax-attn.  1 block x 256.
// ---------------------------------------------------------------------------
__global__ void attn_kernel(const int* __restrict__ pos_p,
                            const float* __restrict__ w_qn,
                            const float* __restrict__ w_kn,
                            const float* __restrict__ past_k,
                            const float* __restrict__ past_v,
                            float* __restrict__ out_k,
                            float* __restrict__ out_v) {
    __shared__ float qs[NH * HD];
    __shared__ float ks[NKV * HD];
    __shared__ float vs[NKV * HD];
    __shared__ float sc[NH][MAXS];
    int tid = threadIdx.x, warp = tid >> 5, lane = tid & 31;
    int pos = pos_p[0];

    const float NEG_LN_THETA_OVER_64 = -13.815510557964274f / 64.f;  // -ln(1e6)/64
    float f0 = (float)pos * expf((float)lane * NEG_LN_THETA_OVER_64);
    float f1 = (float)pos * expf((float)(lane + 32) * NEG_LN_THETA_OVER_64);
    float c0 = cosf(f0), s0 = sinf(f0), c1 = cosf(f1), s1 = sinf(f1);

    {
        int kvh = warp;
        const float* kr = g_kraw + kvh * HD;
        float r0 = kr[lane], r1 = kr[lane + 32], r2 = kr[lane + 64], r3 = kr[lane + 96];
        float ssq = warp_sum(r0 * r0 + r1 * r1 + r2 * r2 + r3 * r3);
        float inv = rsqrtf(ssq * (1.f / HD) + EPS);
        float k0 = r0 * inv * w_kn[lane];
        float k1 = r1 * inv * w_kn[lane + 32];
        float k2 = r2 * inv * w_kn[lane + 64];
        float k3 = r3 * inv * w_kn[lane + 96];
        float o0 = k0 * c0 - k2 * s0;
        float o2 = k2 * c0 + k0 * s0;
        float o1 = k1 * c1 - k3 * s1;
        float o3 = k3 * c1 + k1 * s1;
        float* kd = ks + kvh * HD;
        kd[lane] = o0; kd[lane + 32] = o1; kd[lane + 64] = o2; kd[lane + 96] = o3;
        float* okp = out_k + (size_t)(kvh * MAXS + pos) * HD;
        okp[lane] = o0; okp[lane + 32] = o1; okp[lane + 64] = o2; okp[lane + 96] = o3;

        const float* vr = g_vraw + kvh * HD;
        float v0 = vr[lane], v1 = vr[lane + 32], v2 = vr[lane + 64], v3 = vr[lane + 96];
        float* vd = vs + kvh * HD;
        vd[lane] = v0; vd[lane + 32] = v1; vd[lane + 64] = v2; vd[lane + 96] = v3;
        float* ovp = out_v + (size_t)(kvh * MAXS + pos) * HD;
        ovp[lane] = v0; ovp[lane + 32] = v1; ovp[lane + 64] = v2; ovp[lane + 96] = v3;
    }

#pragma unroll
    for (int hh = 0; hh < 2; hh++) {
        int hq = warp * 2 + hh;
        const float* qr = g_qraw + hq * HD;
        float r0 = qr[lane], r1 = qr[lane + 32], r2 = qr[lane + 64], r3 = qr[lane + 96];
        float ssq = warp_sum(r0 * r0 + r1 * r1 + r2 * r2 + r3 * r3);
        float inv = rsqrtf(ssq * (1.f / HD) + EPS);
        float q0 = r0 * inv * w_qn[lane];
        float q1 = r1 * inv * w_qn[lane + 32];
        float q2 = r2 * inv * w_qn[lane + 64];
        float q3 = r3 * inv * w_qn[lane + 96];
        float* qd = qs + hq * HD;
        qd[lane]      = q0 * c0 - q2 * s0;
        qd[lane + 64] = q2 * c0 + q0 * s0;
        qd[lane + 32] = q1 * c1 - q3 * s1;
        qd[lane + 96] = q3 * c1 + q1 * s1;
    }
    __syncthreads();

    const float scale = 0.08838834764831845f;  // 1/sqrt(128)
#pragma unroll
    for (int hh = 0; hh < 2; hh++) {
        int hq = warp * 2 + hh;
        int kvh = hq >> 1;
        const float* qd = qs + hq * HD;
        float q0 = qd[lane], q1 = qd[lane + 32], q2 = qd[lane + 64], q3 = qd[lane + 96];
        for (int t = 0; t <= pos; t++) {
            const float* kt = (t == pos) ? (ks + kvh * HD)
                                         : (past_k + (size_t)(kvh * MAXS + t) * HD);
            float p = q0 * kt[lane] + q1 * kt[lane + 32] + q2 * kt[lane + 64] + q3 * kt[lane + 96];
            p = warp_sum(p);
            if (lane == 0) sc[hq][t] = p;
        }
        __syncwarp();
        float v = (lane <= pos) ? sc[hq][lane] * scale : -INFINITY;
        float m = v;
#pragma unroll
        for (int o = 16; o; o >>= 1) m = fmaxf(m, __shfl_xor_sync(0xffffffffu, m, o));
        float e = (lane <= pos) ? expf(v - m) : 0.f;
        float sum = warp_sum(e);
        float p = e / sum;
        float a0 = 0.f, a1 = 0.f, a2 = 0.f, a3 = 0.f;
        for (int t = 0; t <= pos; t++) {
            float pt = __shfl_sync(0xffffffffu, p, t);
            const float* vt = (t == pos) ? (vs + kvh * HD)
                                         : (past_v + (size_t)(kvh * MAXS + t) * HD);
            a0 += pt * vt[lane]; a1 += pt * vt[lane + 32];
            a2 += pt * vt[lane + 64]; a3 += pt * vt[lane + 96];
        }
        float* ad = g_attn + hq * HD;
        ad[lane] = a0; ad[lane + 32] = a1; ad[lane + 64] = a2; ad[lane + 96] = a3;
    }
}

// ---------------------------------------------------------------------------
// O projection + residual: x += wo @ attn.  block-per-row, grid 1024 x 512.
// ---------------------------------------------------------------------------
__global__ void __launch_bounds__(512) o_kernel(const float* __restrict__ wo) {
    __shared__ float red[16];
    int row = blockIdx.x;
    int tid = threadIdx.x, lane = tid & 31, wp = tid >> 5;
    float4 a = ((const float4*)(wo + (size_t)row * (NH * HD)))[tid];
    float4 b = ((const float4*)g_attn)[tid];
    float acc = a.x * b.x + a.y * b.y + a.z * b.z + a.w * b.w;
    acc = warp_sum(acc);
    if (lane == 0) red[wp] = acc;
    __syncthreads();
    if (tid == 0) {
        float tot = 0.f;
#pragma unroll
        for (int i = 0; i < 16; i++) tot += red[i];
        g_x[row] += tot;
    }
}

// ---------------------------------------------------------------------------
// Gate/Up: t = silu(wg@h) * (wu@h).  block-per-row, grid 3072 x 256.
// ---------------------------------------------------------------------------
__global__ void __launch_bounds__(256) gu_kernel(const float* __restrict__ wg,
                                                 const float* __restrict__ wu) {
    __shared__ float rg[8], ru[8];
    int row = blockIdx.x;
    int tid = threadIdx.x, lane = tid & 31, wp = tid >> 5;
    float4 b = ((const float4*)g_h)[tid];
    float4 a = ((const float4*)(wg + (size_t)row * H))[tid];
    float4 c = ((const float4*)(wu + (size_t)row * H))[tid];
    float ag = a.x * b.x + a.y * b.y + a.z * b.z + a.w * b.w;
    float au = c.x * b.x + c.y * b.y + c.z * b.z + c.w * b.w;
    ag = warp_sum(ag);
    au = warp_sum(au);
    if (lane == 0) { rg[wp] = ag; ru[wp] = au; }
    __syncthreads();
    if (tid == 0) {
        float tg = 0.f, tu = 0.f;
#pragma unroll
        for (int i = 0; i < 8; i++) { tg += rg[i]; tu += ru[i]; }
        float sg = tg / (1.f + expf(-tg));
        g_t[row] = sg * tu;
    }
}

// ---------------------------------------------------------------------------
// Down + residual: x += wd @ t.  block-per-row, grid 1024 x 768.
// ---------------------------------------------------------------------------
__global__ void __launch_bounds__(768) down_kernel(const float* __restrict__ wd) {
    __shared__ float red[24];
    int row = blockIdx.x;
    int tid = threadIdx.x, lane = tid & 31, wp = tid >> 5;
    float4 a = ((const float4*)(wd + (size_t)row * II))[tid];
    float4 b = ((const float4*)g_t)[tid];
    float acc = a.x * b.x + a.y * b.y + a.z * b.z + a.w * b.w;
    acc = warp_sum(acc);
    if (lane == 0) red[wp] = acc;
    __syncthreads();
    if (tid == 0) {
        float tot = 0.f;
#pragma unroll
        for (int i = 0; i < 24; i++) tot += red[i];
        g_x[row] += tot;
    }
}

// ---------------------------------------------------------------------------
// Final: out = rms(x, w_onorm).  1 block x 1024.
// ---------------------------------------------------------------------------
__global__ void final_kernel(const float* __restrict__ wonorm, float* __restrict__ out) {
    __shared__ float red[32];
    int tid = threadIdx.x;
    float xv = g_x[tid];
    float ssq = warp_sum(xv * xv);
    int lane = tid & 31, wp = tid >> 5;
    if (lane == 0) red[wp] = ssq;
    __syncthreads();
    if (wp == 0) {
        float t = red[lane];
        t = warp_sum(t);
        if (lane == 0) red[0] = rsqrtf(t * (1.f / H) + EPS);
    }
    __syncthreads();
    out[tid] = xv * red[0] * wonorm[tid];
}

extern "C" void kernel_launch(void* const* d_in, const int* in_sizes, int n_in,
                              void* d_out, int out_size) {
    const float* hs     = (const float*)d_in[0];
    const int*   pos    = (const int*)d_in[1];
    const float* pk     = (const float*)d_in[2];
    const float* pv     = (const float*)d_in[3];
    const float* wiln   = (const float*)d_in[4];
    const float* wpaln  = (const float*)d_in[5];
    const float* wq     = (const float*)d_in[6];
    const float* wk     = (const float*)d_in[7];
    const float* wv     = (const float*)d_in[8];
    const float* wo     = (const float*)d_in[9];
    const float* wqn    = (const float*)d_in[10];
    const float* wkn    = (const float*)d_in[11];
    const float* wg     = (const float*)d_in[12];
    const float* wu     = (const float*)d_in[13];
    const float* wd     = (const float*)d_in[14];
    const float* wonorm = (const float*)d_in[15];

    float* out   = (float*)d_out;
    float* out_k = out + H;
    float* out_v = out_k + (size_t)LL * NKV * MAXS * HD;

    const size_t cache_bytes = (size_t)LL * NKV * MAXS * HD * sizeof(float);
    cudaMemcpyAsync(out_k, pk, cache_bytes, cudaMemcpyDeviceToDevice, 0);
    cudaMemcpyAsync(out_v, pv, cache_bytes, cudaMemcpyDeviceToDevice, 0);

    init_x<<<1, 1024>>>(hs);

    for (int l = 0; l < LL; l++) {
        size_t lofs = (size_t)l * NKV * MAXS * HD;
        norm_kernel<<<1, 1024>>>(wiln + l * H);
        qkv_kernel<<<4096, 256>>>(wq + (size_t)l * NH * HD * H,
                                  wk + (size_t)l * NKV * HD * H,
                                  wv + (size_t)l * NKV * HD * H);
        attn_kernel<<<1, 256>>>(pos, wqn + l * HD, wkn + l * HD,
                                pk + lofs, pv + lofs,
                                out_k + lofs, out_v + lofs);
        o_kernel<<<1024, 512>>>(wo + (size_t)l * H * NH * HD);
        norm_kernel<<<1, 1024>>>(wpaln + l * H);
        gu_kernel<<<3072, 256>>>(wg + (size_t)l * II * H,
                                 wu + (size_t)l * II * H);
        down_kernel<<<1024, 768>>>(wd + (size_t)l * H * II);
    }
    final_kernel<<<1, 1024>>>(wonorm, out);
}

// round 3
// speedup vs baseline: 1.6955x; 1.6955x over previous
#include <cuda_runtime.h>
#include <math.h>

#define H    1024
#define NH   16
#define NKV  8
#define HD   128
#define II   3072
#define MAXS 16
#define LL   5
#define EPS  1e-6f

// Residual / activation scratch (allocation-free: __device__ globals)
__device__ float g_x[H];
__device__ float g_h[H];
__device__ float g_qraw[NH * HD];
__device__ float g_kraw[NKV * HD];
__device__ float g_vraw[NKV * HD];
__device__ float g_attn[NH * HD];
__device__ float g_t[II];

__device__ __forceinline__ float warp_sum(float v) {
#pragma unroll
    for (int o = 16; o; o >>= 1) v += __shfl_xor_sync(0xffffffffu, v, o);
    return v;
}

__global__ void init_x(const float* __restrict__ hs) {
    g_x[threadIdx.x] = hs[threadIdx.x];
}

// ---------------------------------------------------------------------------
// norm: g_h = rms(g_x, w).  1 block x 1024.
// ---------------------------------------------------------------------------
__global__ void norm_kernel(const float* __restrict__ w) {
    __shared__ float red[32];
    int tid = threadIdx.x;
    float xv = g_x[tid];
    float ssq = warp_sum(xv * xv);
    int lane = tid & 31, wp = tid >> 5;
    if (lane == 0) red[wp] = ssq;
    __syncthreads();
    if (wp == 0) {
        float t = red[lane];
        t = warp_sum(t);
        if (lane == 0) red[0] = rsqrtf(t * (1.f / H) + EPS);
    }
    __syncthreads();
    g_h[tid] = xv * red[0] * w[tid];
}

// ---------------------------------------------------------------------------
// QKV GEMV: block-per-row.  grid 4096 x 256.
// ---------------------------------------------------------------------------
__global__ void __launch_bounds__(256) qkv_kernel(const float* __restrict__ wq,
                                                  const float* __restrict__ wk,
                                                  const float* __restrict__ wv) {
    __shared__ float red[8];
    int row = blockIdx.x;
    int tid = threadIdx.x, lane = tid & 31, wp = tid >> 5;

    const float* wrow;
    float* outp;
    if (row < NH * HD)                 { wrow = wq + (size_t)row * H; outp = g_qraw + row; }
    else if (row < NH * HD + NKV * HD) { int r = row - NH * HD; wrow = wk + (size_t)r * H; outp = g_kraw + r; }
    else                               { int r = row - NH * HD - NKV * HD; wrow = wv + (size_t)r * H; outp = g_vraw + r; }

    float4 a = ((const float4*)wrow)[tid];
    float4 b = ((const float4*)g_h)[tid];
    float acc = a.x * b.x + a.y * b.y + a.z * b.z + a.w * b.w;
    acc = warp_sum(acc);
    if (lane == 0) red[wp] = acc;
    __syncthreads();
    if (tid == 0) {
        float tot = 0.f;
#pragma unroll
        for (int i = 0; i < 8; i++) tot += red[i];
        *outp = tot;
    }
}

// ---------------------------------------------------------------------------
// Attention v2: grid NH=16 blocks x 128 threads (block per q-head).
// All position loads issued in parallel; K rope recomputed per head pair.
// ---------------------------------------------------------------------------
__global__ void __launch_bounds__(128) attn_kernel(const int* __restrict__ pos_p,
                                                   const float* __restrict__ w_qn,
                                                   const float* __restrict__ w_kn,
                                                   const float* __restrict__ past_k,
                                                   const float* __restrict__ past_v,
                                                   float* __restrict__ out_k,
                                                   float* __restrict__ out_v) {
    __shared__ float k_s[HD], q_s[HD], v_s[HD];
    __shared__ float tmp_k[HD], tmp_q[HD];
    __shared__ float redk[4], redq[4];
    __shared__ float p_s[MAXS];

    int hq  = blockIdx.x;
    int kvh = hq >> 1;
    int tid = threadIdx.x, lane = tid & 31, wp = tid >> 5;
    int pos = pos_p[0];

    // Raw vectors (thread per dim)
    float kv = g_kraw[kvh * HD + tid];
    float qv = g_qraw[hq * HD + tid];
    float vv = g_vraw[kvh * HD + tid];

    // Block-reduce sum of squares for k and q
    float sk = warp_sum(kv * kv);
    float sq = warp_sum(qv * qv);
    if (lane == 0) { redk[wp] = sk; redq[wp] = sq; }
    __syncthreads();
    float sumk = redk[0] + redk[1] + redk[2] + redk[3];
    float sumq = redq[0] + redq[1] + redq[2] + redq[3];
    float invk = rsqrtf(sumk * (1.f / HD) + EPS);
    float invq = rsqrtf(sumq * (1.f / HD) + EPS);
    float kn = kv * invk * w_kn[tid];
    float qn = qv * invq * w_qn[tid];

    // RoPE: partner = tid ^ 64, sign = -1 for tid<64 else +1, angle idx = tid % 64
    tmp_k[tid] = kn; tmp_q[tid] = qn;
    __syncthreads();
    float pk_ = tmp_k[tid ^ 64];
    float pq_ = tmp_q[tid ^ 64];
    const float NEG_LN_THETA_OVER_64 = -13.815510557964274f / 64.f;  // -ln(1e6)/64
    float f = (float)pos * expf((float)(tid & 63) * NEG_LN_THETA_OVER_64);
    float c = cosf(f), s = sinf(f);
    float sign = (tid < 64) ? -1.f : 1.f;
    float k_rope = kn * c + sign * pk_ * s;
    float q_rope = qn * c + sign * pq_ * s;

    k_s[tid] = k_rope;
    q_s[tid] = q_rope;
    v_s[tid] = vv;
    if ((hq & 1) == 0) {
        // one block per kv head writes the cache slot
        out_k[(size_t)(kvh * MAXS + pos) * HD + tid] = k_rope;
        out_v[(size_t)(kvh * MAXS + pos) * HD + tid] = vv;
    }
    __syncthreads();

    // Scores: warp wp handles t = wp + 4*i  (all loads issued concurrently)
    const float scale = 0.08838834764831845f;  // 1/sqrt(128)
    float q0 = q_s[lane], q1 = q_s[lane + 32], q2 = q_s[lane + 64], q3 = q_s[lane + 96];
    const float* kbase = past_k + (size_t)kvh * MAXS * HD;
#pragma unroll
    for (int i = 0; i < 4; i++) {
        int t = wp + 4 * i;
        const float* kt = (t == pos) ? k_s : (kbase + (size_t)t * HD);
        float d = q0 * kt[lane] + q1 * kt[lane + 32] + q2 * kt[lane + 64] + q3 * kt[lane + 96];
        d = warp_sum(d);
        if (lane == 0 && t <= pos) p_s[t] = d * scale;
    }
    __syncthreads();

    // Softmax over positions (warp 0)
    if (wp == 0) {
        float v = (lane <= pos) ? p_s[lane] : -INFINITY;
        float m = v;
#pragma unroll
        for (int o = 16; o; o >>= 1) m = fmaxf(m, __shfl_xor_sync(0xffffffffu, m, o));
        float e = (lane <= pos) ? expf(v - m) : 0.f;
        float sum = warp_sum(e);
        if (lane < MAXS) p_s[lane] = e / sum;
    }
    __syncthreads();

    // Output: thread per dim, all 16 V loads issued concurrently (masked)
    const float* vbase = past_v + (size_t)kvh * MAXS * HD;
    float acc = 0.f;
#pragma unroll
    for (int t = 0; t < MAXS; t++) {
        float pt = (t <= pos) ? p_s[t] : 0.f;
        float vt = (t == pos) ? v_s[tid] : vbase[(size_t)t * HD + tid];
        acc += pt * vt;
    }
    g_attn[hq * HD + tid] = acc;
}

// ---------------------------------------------------------------------------
// O projection + residual: x += wo @ attn.  block-per-row, grid 1024 x 512.
// ---------------------------------------------------------------------------
__global__ void __launch_bounds__(512) o_kernel(const float* __restrict__ wo) {
    __shared__ float red[16];
    int row = blockIdx.x;
    int tid = threadIdx.x, lane = tid & 31, wp = tid >> 5;
    float4 a = ((const float4*)(wo + (size_t)row * (NH * HD)))[tid];
    float4 b = ((const float4*)g_attn)[tid];
    float acc = a.x * b.x + a.y * b.y + a.z * b.z + a.w * b.w;
    acc = warp_sum(acc);
    if (lane == 0) red[wp] = acc;
    __syncthreads();
    if (tid == 0) {
        float tot = 0.f;
#pragma unroll
        for (int i = 0; i < 16; i++) tot += red[i];
        g_x[row] += tot;
    }
}

// ---------------------------------------------------------------------------
// Gate/Up: t = silu(wg@h) * (wu@h).  block-per-row, grid 3072 x 256.
// ---------------------------------------------------------------------------
__global__ void __launch_bounds__(256) gu_kernel(const float* __restrict__ wg,
                                                 const float* __restrict__ wu) {
    __shared__ float rg[8], ru[8];
    int row = blockIdx.x;
    int tid = threadIdx.x, lane = tid & 31, wp = tid >> 5;
    float4 b = ((const float4*)g_h)[tid];
    float4 a = ((const float4*)(wg + (size_t)row * H))[tid];
    float4 c = ((const float4*)(wu + (size_t)row * H))[tid];
    float ag = a.x * b.x + a.y * b.y + a.z * b.z + a.w * b.w;
    float au = c.x * b.x + c.y * b.y + c.z * b.z + c.w * b.w;
    ag = warp_sum(ag);
    au = warp_sum(au);
    if (lane == 0) { rg[wp] = ag; ru[wp] = au; }
    __syncthreads();
    if (tid == 0) {
        float tg = 0.f, tu = 0.f;
#pragma unroll
        for (int i = 0; i < 8; i++) { tg += rg[i]; tu += ru[i]; }
        float sg = tg / (1.f + expf(-tg));
        g_t[row] = sg * tu;
    }
}

// ---------------------------------------------------------------------------
// Down + residual: x += wd @ t.  block-per-row, grid 1024 x 768.
// ---------------------------------------------------------------------------
__global__ void __launch_bounds__(768) down_kernel(const float* __restrict__ wd) {
    __shared__ float red[24];
    int row = blockIdx.x;
    int tid = threadIdx.x, lane = tid & 31, wp = tid >> 5;
    float4 a = ((const float4*)(wd + (size_t)row * II))[tid];
    float4 b = ((const float4*)g_t)[tid];
    float acc = a.x * b.x + a.y * b.y + a.z * b.z + a.w * b.w;
    acc = warp_sum(acc);
    if (lane == 0) red[wp] = acc;
    __syncthreads();
    if (tid == 0) {
        float tot = 0.f;
#pragma unroll
        for (int i = 0; i < 24; i++) tot += red[i];
        g_x[row] += tot;
    }
}

// ---------------------------------------------------------------------------
// Final: out = rms(x, w_onorm).  1 block x 1024.
// ---------------------------------------------------------------------------
__global__ void final_kernel(const float* __restrict__ wonorm, float* __restrict__ out) {
    __shared__ float red[32];
    int tid = threadIdx.x;
    float xv = g_x[tid];
    float ssq = warp_sum(xv * xv);
    int lane = tid & 31, wp = tid >> 5;
    if (lane == 0) red[wp] = ssq;
    __syncthreads();
    if (wp == 0) {
        float t = red[lane];
        t = warp_sum(t);
        if (lane == 0) red[0] = rsqrtf(t * (1.f / H) + EPS);
    }
    __syncthreads();
    out[tid] = xv * red[0] * wonorm[tid];
}

extern "C" void kernel_launch(void* const* d_in, const int* in_sizes, int n_in,
                              void* d_out, int out_size) {
    const float* hs     = (const float*)d_in[0];
    const int*   pos    = (const int*)d_in[1];
    const float* pk     = (const float*)d_in[2];
    const float* pv     = (const float*)d_in[3];
    const float* wiln   = (const float*)d_in[4];
    const float* wpaln  = (const float*)d_in[5];
    const float* wq     = (const float*)d_in[6];
    const float* wk     = (const float*)d_in[7];
    const float* wv     = (const float*)d_in[8];
    const float* wo     = (const float*)d_in[9];
    const float* wqn    = (const float*)d_in[10];
    const float* wkn    = (const float*)d_in[11];
    const float* wg     = (const float*)d_in[12];
    const float* wu     = (const float*)d_in[13];
    const float* wd     = (const float*)d_in[14];
    const float* wonorm = (const float*)d_in[15];

    float* out   = (float*)d_out;
    float* out_k = out + H;
    float* out_v = out_k + (size_t)LL * NKV * MAXS * HD;

    const size_t cache_bytes = (size_t)LL * NKV * MAXS * HD * sizeof(float);
    cudaMemcpyAsync(out_k, pk, cache_bytes, cudaMemcpyDeviceToDevice, 0);
    cudaMemcpyAsync(out_v, pv, cache_bytes, cudaMemcpyDeviceToDevice, 0);

    init_x<<<1, 1024>>>(hs);

    for (int l = 0; l < LL; l++) {
        size_t lofs = (size_t)l * NKV * MAXS * HD;
        norm_kernel<<<1, 1024>>>(wiln + l * H);
        qkv_kernel<<<4096, 256>>>(wq + (size_t)l * NH * HD * H,
                                  wk + (size_t)l * NKV * HD * H,
                                  wv + (size_t)l * NKV * HD * H);
        attn_kernel<<<NH, 128>>>(pos, wqn + l * HD, wkn + l * HD,
                                 pk + lofs, pv + lofs,
                                 out_k + lofs, out_v + lofs);
        o_kernel<<<1024, 512>>>(wo + (size_t)l * H * NH * HD);
        norm_kernel<<<1, 1024>>>(wpaln + l * H);
        gu_kernel<<<3072, 256>>>(wg + (size_t)l * II * H,
                                 wu + (size_t)l * II * H);
        down_kernel<<<1024, 768>>>(wd + (size_t)l * H * II);
    }
    final_kernel<<<1, 1024>>>(wonorm, out);
}

// round 4
// speedup vs baseline: 1.7111x; 1.0092x over previous
#include <cuda_runtime.h>
#include <math.h>

#define H    1024
#define NH   16
#define NKV  8
#define HD   128
#define II   3072
#define MAXS 16
#define LL   5
#define EPS  1e-6f
#define GRID 148
#define TPB  1024

// Persistent state (allocation-free: __device__ globals)
__device__ float g_x[H];
__device__ float g_qraw[NH * HD];
__device__ float g_kraw[NKV * HD];
__device__ float g_vraw[NKV * HD];
__device__ float g_attn[NH * HD];
__device__ float g_t[II];
__device__ unsigned g_count;
__device__ unsigned g_release;

__device__ __forceinline__ float warp_sum(float v) {
#pragma unroll
    for (int o = 16; o; o >>= 1) v += __shfl_xor_sync(0xffffffffu, v, o);
    return v;
}

__global__ void reset_kernel() {
    g_count = 0;
    g_release = 0;
}

// Monotonic-epoch grid barrier. Grid must be fully co-resident (148 blocks,
// 1 per SM, <=64 regs/thread, guaranteed wave-1 placement).
__device__ __forceinline__ void grid_barrier(int& epoch) {
    __syncthreads();
    epoch++;
    if (threadIdx.x == 0) {
        __threadfence();
        unsigned a = atomicAdd(&g_count, 1u) + 1u;
        if (a == (unsigned)(GRID * epoch)) {
            atomicExch(&g_release, (unsigned)epoch);
        } else {
            while (((volatile unsigned*)&g_release)[0] < (unsigned)epoch) { }
        }
        __threadfence();
    }
    __syncthreads();
}

// Block-local RMSNorm of g_x with weight w -> h_s[0..1023].
__device__ __forceinline__ void block_norm(const float* __restrict__ w,
                                           float* h_s, float* red) {
    int tid = threadIdx.x;
    float xv = g_x[tid];
    float ssq = warp_sum(xv * xv);
    if ((tid & 31) == 0) red[tid >> 5] = ssq;
    __syncthreads();
    if (tid < 32) {
        float t = red[tid];
        t = warp_sum(t);
        if (tid == 0) red[0] = rsqrtf(t * (1.f / H) + EPS);
    }
    __syncthreads();
    float inv = red[0];
    h_s[tid] = xv * inv * w[tid];
    __syncthreads();
}

__global__ void __launch_bounds__(TPB, 1)
persistent_kernel(const float* __restrict__ hs,
                  const int* __restrict__ pos_p,
                  const float* __restrict__ pk,
                  const float* __restrict__ pv,
                  const float* __restrict__ wiln,
                  const float* __restrict__ wpaln,
                  const float* __restrict__ wq,
                  const float* __restrict__ wk,
                  const float* __restrict__ wv,
                  const float* __restrict__ wo,
                  const float* __restrict__ wqn,
                  const float* __restrict__ wkn,
                  const float* __restrict__ wg,
                  const float* __restrict__ wu,
                  const float* __restrict__ wd,
                  const float* __restrict__ wonorm,
                  float* __restrict__ out,
                  float* __restrict__ out_k,
                  float* __restrict__ out_v) {
    __shared__ float s_vec[II];     // reused: h (1024), attn (2048), t (3072), attn smem
    __shared__ float red[32];
    __shared__ float p_s[MAXS];
    __shared__ float red2[8];

    int tid  = threadIdx.x;
    int bid  = blockIdx.x;
    int lane = tid & 31;
    int wid  = tid >> 5;
    int row  = wid * GRID + bid;    // unique in [0, 4736)
    int epoch = 0;

    // ---- init: block 0 loads residual ----
    if (bid == 0) g_x[tid] = hs[tid];
    grid_barrier(epoch);

    int pos = pos_p[0];

    for (int l = 0; l < LL; l++) {
        const float* wq_l = wq + (size_t)l * NH * HD * H;
        const float* wk_l = wk + (size_t)l * NKV * HD * H;
        const float* wv_l = wv + (size_t)l * NKV * HD * H;
        const float* wo_l = wo + (size_t)l * H * NH * HD;
        const float* wg_l = wg + (size_t)l * II * H;
        const float* wu_l = wu + (size_t)l * II * H;
        const float* wd_l = wd + (size_t)l * H * II;
        size_t lofs = (size_t)l * NKV * MAXS * HD;

        // ============ P1: h = rms(x, wiln); qkv GEMV (warp per row) ============
        block_norm(wiln + l * H, s_vec, red);
        if (row < NH * HD + 2 * NKV * HD) {
            const float* wrow;
            float* outp;
            if (row < NH * HD)                 { wrow = wq_l + (size_t)row * H; outp = g_qraw + row; }
            else if (row < NH * HD + NKV * HD) { int r = row - NH * HD; wrow = wk_l + (size_t)r * H; outp = g_kraw + r; }
            else                               { int r = row - NH * HD - NKV * HD; wrow = wv_l + (size_t)r * H; outp = g_vraw + r; }
            const float4* w4 = (const float4*)wrow;
            const float4* h4 = (const float4*)s_vec;
            float acc = 0.f;
#pragma unroll
            for (int j = 0; j < 8; j++) {
                float4 a = w4[lane + 32 * j];
                float4 b = h4[lane + 32 * j];
                acc += a.x * b.x + a.y * b.y + a.z * b.z + a.w * b.w;
            }
            acc = warp_sum(acc);
            if (lane == 0) *outp = acc;
        }
        grid_barrier(epoch);

        // ============ P2: attention (blocks 0..15, threads 0..127) ============
        if (bid < NH) {
            int hq  = bid;
            int kvh = hq >> 1;
            bool act = tid < 128;
            int wp4 = wid;  // active warps 0..3

            float* k_s  = s_vec;          // 128
            float* q_s  = s_vec + 128;    // 128
            float* v_s  = s_vec + 256;    // 128
            float* tmpk = s_vec + 384;    // 128
            float* tmpq = s_vec + 512;    // 128

            float kv = 0.f, qv = 0.f, vv = 0.f;
            if (act) {
                kv = g_kraw[kvh * HD + tid];
                qv = g_qraw[hq * HD + tid];
                vv = g_vraw[kvh * HD + tid];
                float sk = warp_sum(kv * kv);
                float sq = warp_sum(qv * qv);
                if (lane == 0) { red2[wp4] = sk; red2[4 + wp4] = sq; }
            }
            __syncthreads();
            if (act) {
                float sumk = red2[0] + red2[1] + red2[2] + red2[3];
                float sumq = red2[4] + red2[5] + red2[6] + red2[7];
                float invk = rsqrtf(sumk * (1.f / HD) + EPS);
                float invq = rsqrtf(sumq * (1.f / HD) + EPS);
                float kn = kv * invk * wkn[l * HD + tid];
                float qn = qv * invq * wqn[l * HD + tid];
                tmpk[tid] = kn; tmpq[tid] = qn;
            }
            __syncthreads();
            if (act) {
                float kn = tmpk[tid], qn = tmpq[tid];
                float pk_ = tmpk[tid ^ 64];
                float pq_ = tmpq[tid ^ 64];
                const float NEG_LN_THETA_OVER_64 = -13.815510557964274f / 64.f;
                float f = (float)pos * expf((float)(tid & 63) * NEG_LN_THETA_OVER_64);
                float c = cosf(f), s = sinf(f);
                float sign = (tid < 64) ? -1.f : 1.f;
                float k_rope = kn * c + sign * pk_ * s;
                float q_rope = qn * c + sign * pq_ * s;
                k_s[tid] = k_rope;
                q_s[tid] = q_rope;
                v_s[tid] = vv;
                if ((hq & 1) == 0) {
                    out_k[lofs + (size_t)(kvh * MAXS + pos) * HD + tid] = k_rope;
                    out_v[lofs + (size_t)(kvh * MAXS + pos) * HD + tid] = vv;
                }
            }
            __syncthreads();

            const float scale = 0.08838834764831845f;  // 1/sqrt(128)
            if (act) {
                float q0 = q_s[lane], q1 = q_s[lane + 32], q2 = q_s[lane + 64], q3 = q_s[lane + 96];
                const float* kbase = pk + lofs + (size_t)kvh * MAXS * HD;
#pragma unroll
                for (int i = 0; i < 4; i++) {
                    int t = wp4 + 4 * i;
                    const float* kt = (t == pos) ? k_s : (kbase + (size_t)t * HD);
                    float d = q0 * kt[lane] + q1 * kt[lane + 32] + q2 * kt[lane + 64] + q3 * kt[lane + 96];
                    d = warp_sum(d);
                    if (lane == 0 && t <= pos) p_s[t] = d * scale;
                }
            }
            __syncthreads();
            if (tid < 32) {
                float v = (lane <= pos) ? p_s[lane] : -INFINITY;
                float m = v;
#pragma unroll
                for (int o = 16; o; o >>= 1) m = fmaxf(m, __shfl_xor_sync(0xffffffffu, m, o));
                float e = (lane <= pos) ? expf(v - m) : 0.f;
                float sum = warp_sum(e);
                if (lane < MAXS) p_s[lane] = e / sum;
            }
            __syncthreads();
            if (act) {
                const float* vbase = pv + lofs + (size_t)kvh * MAXS * HD;
                float acc = 0.f;
#pragma unroll
                for (int t = 0; t < MAXS; t++) {
                    float pt = (t <= pos) ? p_s[t] : 0.f;
                    float vt = (t == pos) ? v_s[tid] : vbase[(size_t)t * HD + tid];
                    acc += pt * vt;
                }
                g_attn[hq * HD + tid] = acc;
            }
        }
        grid_barrier(epoch);

        // ============ P3: o projection + residual ============
        s_vec[tid]        = g_attn[tid];
        s_vec[tid + 1024] = g_attn[tid + 1024];
        __syncthreads();
        if (row < H) {
            const float4* w4 = (const float4*)(wo_l + (size_t)row * (NH * HD));
            const float4* a4 = (const float4*)s_vec;
            float acc = 0.f;
#pragma unroll 8
            for (int j = 0; j < 16; j++) {
                float4 a = w4[lane + 32 * j];
                float4 b = a4[lane + 32 * j];
                acc += a.x * b.x + a.y * b.y + a.z * b.z + a.w * b.w;
            }
            acc = warp_sum(acc);
            if (lane == 0) g_x[row] += acc;
        }
        grid_barrier(epoch);

        // ============ P4: h = rms(x, wpaln); gate/up GEMV ============
        block_norm(wpaln + l * H, s_vec, red);
        if (row < II) {
            const float4* g4 = (const float4*)(wg_l + (size_t)row * H);
            const float4* u4 = (const float4*)(wu_l + (size_t)row * H);
            const float4* h4 = (const float4*)s_vec;
            float ag = 0.f, au = 0.f;
#pragma unroll
            for (int j = 0; j < 8; j++) {
                float4 b = h4[lane + 32 * j];
                float4 a = g4[lane + 32 * j];
                ag += a.x * b.x + a.y * b.y + a.z * b.z + a.w * b.w;
                float4 cc = u4[lane + 32 * j];
                au += cc.x * b.x + cc.y * b.y + cc.z * b.z + cc.w * b.w;
            }
            ag = warp_sum(ag);
            au = warp_sum(au);
            if (lane == 0) {
                float sg = ag / (1.f + expf(-ag));
                g_t[row] = sg * au;
            }
        }
        grid_barrier(epoch);

        // ============ P5: down + residual ============
        s_vec[tid]        = g_t[tid];
        s_vec[tid + 1024] = g_t[tid + 1024];
        s_vec[tid + 2048] = g_t[tid + 2048];
        __syncthreads();
        if (row < H) {
            const float4* w4 = (const float4*)(wd_l + (size_t)row * II);
            const float4* t4 = (const float4*)s_vec;
            float acc = 0.f;
#pragma unroll 8
            for (int j = 0; j < 24; j++) {
                float4 a = w4[lane + 32 * j];
                float4 b = t4[lane + 32 * j];
                acc += a.x * b.x + a.y * b.y + a.z * b.z + a.w * b.w;
            }
            acc = warp_sum(acc);
            if (lane == 0) g_x[row] += acc;
        }
        grid_barrier(epoch);
    }

    // ---- final: out = rms(x, w_onorm), block 0 ----
    if (bid == 0) {
        float xv = g_x[tid];
        float ssq = warp_sum(xv * xv);
        if (lane == 0) red[wid] = ssq;
        __syncthreads();
        if (tid < 32) {
            float t = red[tid];
            t = warp_sum(t);
            if (tid == 0) red[0] = rsqrtf(t * (1.f / H) + EPS);
        }
        __syncthreads();
        out[tid] = xv * red[0] * wonorm[tid];
    }
}

extern "C" void kernel_launch(void* const* d_in, const int* in_sizes, int n_in,
                              void* d_out, int out_size) {
    const float* hs     = (const float*)d_in[0];
    const int*   pos    = (const int*)d_in[1];
    const float* pk     = (const float*)d_in[2];
    const float* pv     = (const float*)d_in[3];
    const float* wiln   = (const float*)d_in[4];
    const float* wpaln  = (const float*)d_in[5];
    const float* wq     = (const float*)d_in[6];
    const float* wk     = (const float*)d_in[7];
    const float* wv     = (const float*)d_in[8];
    const float* wv_    = wv;
    const float* wo     = (const float*)d_in[9];
    const float* wqn    = (const float*)d_in[10];
    const float* wkn    = (const float*)d_in[11];
    const float* wg     = (const float*)d_in[12];
    const float* wu     = (const float*)d_in[13];
    const float* wd     = (const float*)d_in[14];
    const float* wonorm = (const float*)d_in[15];

    float* out   = (float*)d_out;
    float* out_k = out + H;
    float* out_v = out_k + (size_t)LL * NKV * MAXS * HD;

    const size_t cache_bytes = (size_t)LL * NKV * MAXS * HD * sizeof(float);
    cudaMemcpyAsync(out_k, pk, cache_bytes, cudaMemcpyDeviceToDevice, 0);
    cudaMemcpyAsync(out_v, pv, cache_bytes, cudaMemcpyDeviceToDevice, 0);

    reset_kernel<<<1, 1>>>();
    persistent_kernel<<<GRID, TPB>>>(hs, pos, pk, pv, wiln, wpaln,
                                     wq, wk, wv_, wo, wqn, wkn,
                                     wg, wu, wd, wonorm,
                                     out, out_k, out_v);
}

// round 5
// speedup vs baseline: 1.8158x; 1.0612x over previous
#include <cuda_runtime.h>
#include <math.h>

#define H    1024
#define NH   16
#define NKV  8
#define HD   128
#define II   3072
#define MAXS 16
#define LL   5
#define EPS  1e-6f
#define GRID 148
#define TPB  512
#define NWARP 16
#define NWG  (GRID * NWARP)                      // 2368 warps chip-wide
#define CACHE_F4 ((LL * NKV * MAXS * HD) / 4)    // 20480 float4 per cache

// Persistent state (allocation-free: __device__ globals)
__device__ float g_x[H];
__device__ float g_qraw[NH * HD];
__device__ float g_kraw[NKV * HD];
__device__ float g_vraw[NKV * HD];
__device__ float g_attn[NH * HD];
__device__ float g_gate[II];   // silu(gate) GEMV results
__device__ float g_up[II];     // up GEMV results
__device__ unsigned g_count;
__device__ unsigned g_release;

__device__ __forceinline__ float warp_sum(float v) {
#pragma unroll
    for (int o = 16; o; o >>= 1) v += __shfl_xor_sync(0xffffffffu, v, o);
    return v;
}

__device__ __forceinline__ float dot4(float4 a, float4 b) {
    return a.x * b.x + a.y * b.y + a.z * b.z + a.w * b.w;
}

__global__ void reset_kernel() {
    g_count = 0;
    g_release = 0;
}

// Monotonic-epoch grid barrier; grid is fully co-resident (148 blocks, 1/SM).
__device__ __forceinline__ void grid_barrier(int& epoch) {
    __syncthreads();
    epoch++;
    if (threadIdx.x == 0) {
        __threadfence();
        unsigned a = atomicAdd(&g_count, 1u) + 1u;
        if (a == (unsigned)(GRID * epoch)) {
            atomicExch(&g_release, (unsigned)epoch);
        } else {
            while (((volatile unsigned*)&g_release)[0] < (unsigned)epoch) { }
        }
        __threadfence();
    }
    __syncthreads();
}

// Block-local RMSNorm of g_x with weight w -> h_s[0..1023]. 512 threads.
__device__ __forceinline__ void block_norm(const float* __restrict__ w,
                                           float* h_s, float* red) {
    int tid = threadIdx.x, lane = tid & 31, wid = tid >> 5;
    float x0 = g_x[tid], x1 = g_x[tid + 512];
    float ssq = warp_sum(x0 * x0 + x1 * x1);
    if (lane == 0) red[wid] = ssq;
    __syncthreads();
    if (wid == 0) {
        float t = (lane < NWARP) ? red[lane] : 0.f;
        t = warp_sum(t);
        if (lane == 0) red[0] = rsqrtf(t * (1.f / H) + EPS);
    }
    __syncthreads();
    float inv = red[0];
    h_s[tid]       = x0 * inv * w[tid];
    h_s[tid + 512] = x1 * inv * w[tid + 512];
    __syncthreads();
}

__device__ __forceinline__ const float* qkv_wrow(const float* wq_l, const float* wk_l,
                                                 const float* wv_l, int r) {
    if (r < 2048) return wq_l + (size_t)r * H;
    if (r < 3072) return wk_l + (size_t)(r - 2048) * H;
    return wv_l + (size_t)(r - 3072) * H;
}
__device__ __forceinline__ float* qkv_out(int r) {
    if (r < 2048) return g_qraw + r;
    if (r < 3072) return g_kraw + (r - 2048);
    return g_vraw + (r - 3072);
}

__global__ void __launch_bounds__(TPB, 1)
persistent_kernel(const float* __restrict__ hs,
                  const int* __restrict__ pos_p,
                  const float* __restrict__ pk,
                  const float* __restrict__ pv,
                  const float* __restrict__ wiln,
                  const float* __restrict__ wpaln,
                  const float* __restrict__ wq,
                  const float* __restrict__ wk,
                  const float* __restrict__ wv,
                  const float* __restrict__ wo,
                  const float* __restrict__ wqn,
                  const float* __restrict__ wkn,
                  const float* __restrict__ wg,
                  const float* __restrict__ wu,
                  const float* __restrict__ wd,
                  const float* __restrict__ wonorm,
                  float* __restrict__ out,
                  float* __restrict__ out_k,
                  float* __restrict__ out_v) {
    __shared__ float s_vec[II];       // reused: h / attn vec / t / attn smem
    __shared__ float red[NWARP];
    __shared__ float s_part[NWARP];
    __shared__ float p_s[MAXS];
    __shared__ float red2[8];

    int tid = threadIdx.x, bid = blockIdx.x;
    int lane = tid & 31, wid = tid >> 5;
    int epoch = 0;

    // Row maps (every warp busy in every phase)
    int r0 = wid * GRID + bid;            // [0,2368) : P1 row a, P4 vrow a
    int r1 = r0 + NWG;                    // P1 row b (<4096), P4 vrow b (<4736)
    int r2 = r0 + 2 * NWG;                // P4 vrow c (<7104, valid <6144)
    int prow = (wid >> 1) * GRID + bid;   // [0,1184) : P3/P5 row (valid <1024)
    int half = wid & 1;

    int pos = pos_p[0];

    // ---- prologue: residual init + cache copy + layer-0 P1 prefetch ----
    if (bid == 0) { g_x[tid] = hs[tid]; g_x[tid + 512] = hs[tid + 512]; }
    {
        int ci = bid * TPB + tid;
        if (ci < CACHE_F4) {
            ((float4*)out_k)[ci] = ((const float4*)pk)[ci];
            ((float4*)out_v)[ci] = ((const float4*)pv)[ci];
        }
    }

    float4 A0[8], A1[8];
    {
        const float4* p0 = (const float4*)qkv_wrow(wq, wk, wv, r0);
#pragma unroll
        for (int j = 0; j < 8; j++) A0[j] = p0[lane + 32 * j];
        if (r1 < 4096) {
            const float4* p1 = (const float4*)qkv_wrow(wq, wk, wv, r1);
#pragma unroll
            for (int j = 0; j < 8; j++) A1[j] = p1[lane + 32 * j];
        }
    }
    grid_barrier(epoch);

    for (int l = 0; l < LL; l++) {
        const float* wo_l = wo + (size_t)l * H * NH * HD;
        const float* wg_l = wg + (size_t)l * II * H;
        const float* wu_l = wu + (size_t)l * II * H;
        const float* wd_l = wd + (size_t)l * H * II;
        size_t lofs = (size_t)l * NKV * MAXS * HD;

        // ================= P1: norm + qkv GEMV (prefetched A0/A1) =================
        block_norm(wiln + l * H, s_vec, red);
        {
            const float4* h4 = (const float4*)s_vec;
            float4 B[8];
#pragma unroll
            for (int j = 0; j < 8; j++) B[j] = h4[lane + 32 * j];
            float a0 = 0.f;
#pragma unroll
            for (int j = 0; j < 8; j++) a0 += dot4(A0[j], B[j]);
            a0 = warp_sum(a0);
            if (lane == 0) *qkv_out(r0) = a0;
            if (r1 < 4096) {
                float a1 = 0.f;
#pragma unroll
                for (int j = 0; j < 8; j++) a1 += dot4(A1[j], B[j]);
                a1 = warp_sum(a1);
                if (lane == 0) *qkv_out(r1) = a1;
            }
        }

        // prefetch P3 (wo): half-row per warp, 8 f4/lane
        float4 C[8];
        if (prow < H) {
            const float4* w4 = (const float4*)(wo_l + (size_t)prow * (NH * HD)) + half * 256;
#pragma unroll
            for (int j = 0; j < 8; j++) C[j] = w4[lane + 32 * j];
        }
        grid_barrier(epoch);

        // ================= P2: attention (blocks 0..15, threads 0..127) =================
        if (bid < NH) {
            int hq  = bid;
            int kvh = hq >> 1;
            bool act = tid < 128;
            float* k_s  = s_vec;
            float* q_s  = s_vec + 128;
            float* v_s  = s_vec + 256;
            float* tmpk = s_vec + 384;
            float* tmpq = s_vec + 512;

            float kv = 0.f, qv = 0.f, vv = 0.f;
            if (act) {
                kv = g_kraw[kvh * HD + tid];
                qv = g_qraw[hq * HD + tid];
                vv = g_vraw[kvh * HD + tid];
                float sk = warp_sum(kv * kv);
                float sq = warp_sum(qv * qv);
                if (lane == 0) { red2[wid] = sk; red2[4 + wid] = sq; }
            }
            __syncthreads();
            if (act) {
                float sumk = red2[0] + red2[1] + red2[2] + red2[3];
                float sumq = red2[4] + red2[5] + red2[6] + red2[7];
                float invk = rsqrtf(sumk * (1.f / HD) + EPS);
                float invq = rsqrtf(sumq * (1.f / HD) + EPS);
                tmpk[tid] = kv * invk * wkn[l * HD + tid];
                tmpq[tid] = qv * invq * wqn[l * HD + tid];
            }
            __syncthreads();
            if (act) {
                float kn = tmpk[tid], qn = tmpq[tid];
                float pk_ = tmpk[tid ^ 64];
                float pq_ = tmpq[tid ^ 64];
                const float NEG_LN_THETA_OVER_64 = -13.815510557964274f / 64.f;
                float f = (float)pos * expf((float)(tid & 63) * NEG_LN_THETA_OVER_64);
                float c = cosf(f), s = sinf(f);
                float sign = (tid < 64) ? -1.f : 1.f;
                float k_rope = kn * c + sign * pk_ * s;
                float q_rope = qn * c + sign * pq_ * s;
                k_s[tid] = k_rope;
                q_s[tid] = q_rope;
                v_s[tid] = vv;
                if ((hq & 1) == 0) {
                    out_k[lofs + (size_t)(kvh * MAXS + pos) * HD + tid] = k_rope;
                    out_v[lofs + (size_t)(kvh * MAXS + pos) * HD + tid] = vv;
                }
            }
            __syncthreads();

            const float scale = 0.08838834764831845f;  // 1/sqrt(128)
            if (act) {
                float q0 = q_s[lane], q1 = q_s[lane + 32], q2 = q_s[lane + 64], q3 = q_s[lane + 96];
                const float* kbase = pk + lofs + (size_t)kvh * MAXS * HD;
#pragma unroll
                for (int i = 0; i < 4; i++) {
                    int t = wid + 4 * i;
                    const float* kt = (t == pos) ? k_s : (kbase + (size_t)t * HD);
                    float d = q0 * kt[lane] + q1 * kt[lane + 32] + q2 * kt[lane + 64] + q3 * kt[lane + 96];
                    d = warp_sum(d);
                    if (lane == 0 && t <= pos) p_s[t] = d * scale;
                }
            }
            __syncthreads();
            if (tid < 32) {
                float v = (lane <= pos) ? p_s[lane] : -INFINITY;
                float m = v;
#pragma unroll
                for (int o = 16; o; o >>= 1) m = fmaxf(m, __shfl_xor_sync(0xffffffffu, m, o));
                float e = (lane <= pos) ? expf(v - m) : 0.f;
                float sum = warp_sum(e);
                if (lane < MAXS) p_s[lane] = e / sum;
            }
            __syncthreads();
            if (act) {
                const float* vbase = pv + lofs + (size_t)kvh * MAXS * HD;
                float acc = 0.f;
#pragma unroll
                for (int t = 0; t < MAXS; t++) {
                    float pt = (t <= pos) ? p_s[t] : 0.f;
                    float vt = (t == pos) ? v_s[tid] : vbase[(size_t)t * HD + tid];
                    acc += pt * vt;
                }
                g_attn[hq * HD + tid] = acc;
            }
        }
        grid_barrier(epoch);

        // ================= P3: o-proj + residual (2 warps/row, prefetched C) ========
        s_vec[tid]        = g_attn[tid];
        s_vec[tid + 512]  = g_attn[tid + 512];
        s_vec[tid + 1024] = g_attn[tid + 1024];
        s_vec[tid + 1536] = g_attn[tid + 1536];
        __syncthreads();
        if (prow < H) {
            const float4* a4 = (const float4*)s_vec + half * 256;
            float acc = 0.f;
#pragma unroll
            for (int j = 0; j < 8; j++) acc += dot4(C[j], a4[lane + 32 * j]);
            acc = warp_sum(acc);
            if (lane == 0) s_part[wid] = acc;
        }
        __syncthreads();
        if (prow < H && half == 0 && lane == 0)
            g_x[prow] += s_part[wid] + s_part[wid + 1];

        // prefetch P4 (gate/up virtual rows r0, r1)
        float4 D0[8], D1[8];
        {
            const float* w0 = (r0 < II) ? (wg_l + (size_t)r0 * H) : (wu_l + (size_t)(r0 - II) * H);
            const float4* p0 = (const float4*)w0;
#pragma unroll
            for (int j = 0; j < 8; j++) D0[j] = p0[lane + 32 * j];
            const float* w1 = (r1 < II) ? (wg_l + (size_t)r1 * H) : (wu_l + (size_t)(r1 - II) * H);
            const float4* p1 = (const float4*)w1;
#pragma unroll
            for (int j = 0; j < 8; j++) D1[j] = p1[lane + 32 * j];
        }
        grid_barrier(epoch);

        // ================= P4: norm + gate/up GEMV =================
        block_norm(wpaln + l * H, s_vec, red);
        {
            const float4* h4 = (const float4*)s_vec;
            float4 B[8];
#pragma unroll
            for (int j = 0; j < 8; j++) B[j] = h4[lane + 32 * j];
            float d0 = 0.f, d1 = 0.f;
#pragma unroll
            for (int j = 0; j < 8; j++) { d0 += dot4(D0[j], B[j]); d1 += dot4(D1[j], B[j]); }
            d0 = warp_sum(d0);
            d1 = warp_sum(d1);
            if (lane == 0) {
                // r0 < 2368 -> always a gate row: store silu(gate)
                g_gate[r0] = d0 / (1.f + expf(-d0));
                if (r1 < II) g_gate[r1] = d1 / (1.f + expf(-d1));
                else         g_up[r1 - II] = d1;
            }
            if (r2 < 2 * II) {  // always an up row
                const float4* p2 = (const float4*)(wu_l + (size_t)(r2 - II) * H);
                float d2 = 0.f;
#pragma unroll
                for (int j = 0; j < 8; j++) d2 += dot4(p2[lane + 32 * j], B[j]);
                d2 = warp_sum(d2);
                if (lane == 0) g_up[r2 - II] = d2;
            }
        }

        // prefetch P5 (wd): half-row per warp, 12 f4/lane
        float4 F[12];
        if (prow < H) {
            const float4* w4 = (const float4*)(wd_l + (size_t)prow * II) + half * 384;
#pragma unroll
            for (int j = 0; j < 12; j++) F[j] = w4[lane + 32 * j];
        }
        grid_barrier(epoch);

        // ================= P5: combine t + down GEMV + residual =================
#pragma unroll
        for (int i = 0; i < 6; i++) {
            int idx = tid + 512 * i;
            s_vec[idx] = g_gate[idx] * g_up[idx];
        }
        __syncthreads();
        if (prow < H) {
            const float4* t4 = (const float4*)s_vec + half * 384;
            float acc = 0.f;
#pragma unroll
            for (int j = 0; j < 12; j++) acc += dot4(F[j], t4[lane + 32 * j]);
            acc = warp_sum(acc);
            if (lane == 0) s_part[wid] = acc;
        }
        __syncthreads();
        if (prow < H && half == 0 && lane == 0)
            g_x[prow] += s_part[wid] + s_part[wid + 1];

        // prefetch next layer's P1
        if (l + 1 < LL) {
            const float* wq_n = wq + (size_t)(l + 1) * NH * HD * H;
            const float* wk_n = wk + (size_t)(l + 1) * NKV * HD * H;
            const float* wv_n = wv + (size_t)(l + 1) * NKV * HD * H;
            const float4* p0 = (const float4*)qkv_wrow(wq_n, wk_n, wv_n, r0);
#pragma unroll
            for (int j = 0; j < 8; j++) A0[j] = p0[lane + 32 * j];
            if (r1 < 4096) {
                const float4* p1 = (const float4*)qkv_wrow(wq_n, wk_n, wv_n, r1);
#pragma unroll
                for (int j = 0; j < 8; j++) A1[j] = p1[lane + 32 * j];
            }
        }
        grid_barrier(epoch);
    }

    // ---- final: out = rms(x, w_onorm), block 0 ----
    if (bid == 0) {
        float x0 = g_x[tid], x1 = g_x[tid + 512];
        float ssq = warp_sum(x0 * x0 + x1 * x1);
        if (lane == 0) red[wid] = ssq;
        __syncthreads();
        if (wid == 0) {
            float t = (lane < NWARP) ? red[lane] : 0.f;
            t = warp_sum(t);
            if (lane == 0) red[0] = rsqrtf(t * (1.f / H) + EPS);
        }
        __syncthreads();
        float inv = red[0];
        out[tid]       = x0 * inv * wonorm[tid];
        out[tid + 512] = x1 * inv * wonorm[tid + 512];
    }
}

extern "C" void kernel_launch(void* const* d_in, const int* in_sizes, int n_in,
                              void* d_out, int out_size) {
    const float* hs     = (const float*)d_in[0];
    const int*   pos    = (const int*)d_in[1];
    const float* pk     = (const float*)d_in[2];
    const float* pv     = (const float*)d_in[3];
    const float* wiln   = (const float*)d_in[4];
    const float* wpaln  = (const float*)d_in[5];
    const float* wq     = (const float*)d_in[6];
    const float* wk     = (const float*)d_in[7];
    const float* wv     = (const float*)d_in[8];
    const float* wo     = (const float*)d_in[9];
    const float* wqn    = (const float*)d_in[10];
    const float* wkn    = (const float*)d_in[11];
    const float* wg     = (const float*)d_in[12];
    const float* wu     = (const float*)d_in[13];
    const float* wd     = (const float*)d_in[14];
    const float* wonorm = (const float*)d_in[15];

    float* out   = (float*)d_out;
    float* out_k = out + H;
    float* out_v = out_k + (size_t)LL * NKV * MAXS * HD;

    reset_kernel<<<1, 1>>>();
    persistent_kernel<<<GRID, TPB>>>(hs, pos, pk, pv, wiln, wpaln,
                                     wq, wk, wv, wo, wqn, wkn,
                                     wg, wu, wd, wonorm,
                                     out, out_k, out_v);
}